// round 4
// baseline (speedup 1.0000x reference)
#include <cuda_runtime.h>
#include <cstdint>
#include <cstddef>

// ---------------- problem constants ----------------
#define Bn 8
#define Nn 2304
#define Dd 768
#define Dm 64
#define K_SCALE 0.125f          // Dm^-0.5
#define LN_EPS 1e-5f

// ---------------- scratch (static device globals; no allocation) ----------------
__device__ float g_q[(size_t)Bn * Nn * Dm];          // 4.7 MB
__device__ float g_sim[(size_t)Bn * Nn * Nn];        // 170 MB
__device__ float g_xA[(size_t)Bn * Nn * Dd];         // 56.6 MB (post-LN ping)
__device__ float g_xT[(size_t)Bn * Nn * Dd];         // 56.6 MB (pre-LN temp)

// ---------------- packed fp32x2 helpers (sm_103a FFMA2 path) ----------------
#define PACK2(d, lo, hi) asm("mov.b64 %0, {%1, %2};" : "=l"(d) : "f"(lo), "f"(hi))
#define FMA2(acc, a, b)  asm("fma.rn.f32x2 %0, %1, %2, %0;" : "+l"(acc) : "l"(a), "l"(b))

// ---------------- block reductions ----------------
__device__ __forceinline__ float block_sum256(float v, float* red) {
    #pragma unroll
    for (int o = 16; o; o >>= 1) v += __shfl_xor_sync(0xffffffffu, v, o);
    int tid = threadIdx.x;
    if ((tid & 31) == 0) red[tid >> 5] = v;
    __syncthreads();
    float t = red[0];
    #pragma unroll
    for (int w = 1; w < 8; w++) t += red[w];
    __syncthreads();
    return t;
}

__device__ __forceinline__ float block_max256(float v, float* red) {
    #pragma unroll
    for (int o = 16; o; o >>= 1) v = fmaxf(v, __shfl_xor_sync(0xffffffffu, v, o));
    int tid = threadIdx.x;
    if ((tid & 31) == 0) red[tid >> 5] = v;
    __syncthreads();
    float t = red[0];
    #pragma unroll
    for (int w = 1; w < 8; w++) t = fmaxf(t, red[w]);
    __syncthreads();
    return t;
}

// ======================================================================
// Kernel 1: q = x @ Wq + bq       x:[BN,768]  Wq:[768,64]  q:[BN,64]
// 64-row blocks, 256 threads, 4x4 microtile, K-tile 32.
// ======================================================================
__global__ void __launch_bounds__(256)
qproj_kernel(const float* __restrict__ x, const float* __restrict__ Wq,
             const float* __restrict__ bq, float* __restrict__ q)
{
    __shared__ float As[64][32];   // [m][k]
    __shared__ float Bs[32][64];   // [k][n]
    const int tid = threadIdx.x;
    const int m0  = blockIdx.x * 64;
    const int ty  = tid >> 4, tx = tid & 15;

    float acc[4][4];
    #pragma unroll
    for (int i = 0; i < 4; i++)
        #pragma unroll
        for (int j = 0; j < 4; j++) acc[i][j] = 0.0f;

    for (int kt = 0; kt < Dd; kt += 32) {
        #pragma unroll
        for (int it = 0; it < 8; it++) {
            int idx = tid + it * 256;           // 2048 elems
            int m = idx >> 5, k = idx & 31;
            As[m][k] = x[(size_t)(m0 + m) * Dd + kt + k];
        }
        #pragma unroll
        for (int it = 0; it < 8; it++) {
            int idx = tid + it * 256;
            int k = idx >> 6, n = idx & 63;
            Bs[k][n] = Wq[(size_t)(kt + k) * Dm + n];
        }
        __syncthreads();
        #pragma unroll
        for (int k = 0; k < 32; k++) {
            float a[4], b[4];
            #pragma unroll
            for (int i = 0; i < 4; i++) a[i] = As[ty * 4 + i][k];
            #pragma unroll
            for (int j = 0; j < 4; j++) b[j] = Bs[k][tx * 4 + j];
            #pragma unroll
            for (int i = 0; i < 4; i++)
                #pragma unroll
                for (int j = 0; j < 4; j++) acc[i][j] = fmaf(a[i], b[j], acc[i][j]);
        }
        __syncthreads();
    }
    #pragma unroll
    for (int i = 0; i < 4; i++)
        #pragma unroll
        for (int j = 0; j < 4; j++)
            q[(size_t)(m0 + ty * 4 + i) * Dm + tx * 4 + j] = acc[i][j] + bq[tx * 4 + j];
}

// ======================================================================
// Kernel 2: sim[b,i,j] = scale * dot(q[b,i,:], q[b,j,:])   (K=64)
// 64x64 output tile, 4x4 microtile, f32x2 packed accumulation.
// ======================================================================
__global__ void __launch_bounds__(256)
sim_kernel(const float* __restrict__ q, float* __restrict__ sim)
{
    const int b  = blockIdx.z;
    const int i0 = blockIdx.y * 64;
    const int j0 = blockIdx.x * 64;
    const float* Q = q + (size_t)b * Nn * Dm;

    __shared__ float Qi[64][65];
    __shared__ float Qj[64][65];

    const int tid = threadIdx.x;
    const int ty = tid >> 4, tx = tid & 15;

    #pragma unroll
    for (int it = 0; it < 4; it++) {
        int idx = tid + it * 256;             // 1024 float4s total
        int m = idx >> 4, k4 = idx & 15;
        float4 vi = *(const float4*)&Q[(size_t)(i0 + m) * Dm + k4 * 4];
        float4 vj = *(const float4*)&Q[(size_t)(j0 + m) * Dm + k4 * 4];
        Qi[m][k4 * 4 + 0] = vi.x; Qi[m][k4 * 4 + 1] = vi.y;
        Qi[m][k4 * 4 + 2] = vi.z; Qi[m][k4 * 4 + 3] = vi.w;
        Qj[m][k4 * 4 + 0] = vj.x; Qj[m][k4 * 4 + 1] = vj.y;
        Qj[m][k4 * 4 + 2] = vj.z; Qj[m][k4 * 4 + 3] = vj.w;
    }
    __syncthreads();

    unsigned long long c2[4][2];
    #pragma unroll
    for (int i = 0; i < 4; i++) { c2[i][0] = 0ULL; c2[i][1] = 0ULL; }

    #pragma unroll
    for (int k = 0; k < 64; k++) {
        float a[4], bv[4];
        #pragma unroll
        for (int i = 0; i < 4; i++) a[i]  = Qi[ty * 4 + i][k];
        #pragma unroll
        for (int j = 0; j < 4; j++) bv[j] = Qj[tx * 4 + j][k];
        unsigned long long bb0, bb1;
        PACK2(bb0, bv[0], bv[1]);
        PACK2(bb1, bv[2], bv[3]);
        #pragma unroll
        for (int i = 0; i < 4; i++) {
            unsigned long long aa;
            PACK2(aa, a[i], a[i]);
            FMA2(c2[i][0], aa, bb0);
            FMA2(c2[i][1], aa, bb1);
        }
    }

    float* S = sim + (size_t)b * Nn * Nn;
    #pragma unroll
    for (int i = 0; i < 4; i++) {
        float2 p0 = *(float2*)&c2[i][0];
        float2 p1 = *(float2*)&c2[i][1];
        float4 o = make_float4(p0.x * K_SCALE, p0.y * K_SCALE,
                               p1.x * K_SCALE, p1.y * K_SCALE);
        *(float4*)&S[(size_t)(i0 + ty * 4 + i) * Nn + j0 + tx * 4] = o;
    }
}

// ======================================================================
// Kernel 3: row-wise softmax over sim, in place. One block per (b,n) row.
// Row of 2304 held in registers (9 per thread).
// ======================================================================
__global__ void __launch_bounds__(256)
softmax_kernel(float* __restrict__ sim)
{
    __shared__ float red[8];
    const size_t row = blockIdx.x;
    float* p = sim + row * (size_t)Nn;
    const int tid = threadIdx.x;

    float v[9];
    #pragma unroll
    for (int i = 0; i < 9; i++) v[i] = p[tid + i * 256];

    float m = -3.0e38f;
    #pragma unroll
    for (int i = 0; i < 9; i++) m = fmaxf(m, v[i]);
    m = block_max256(m, red);

    float s = 0.0f;
    #pragma unroll
    for (int i = 0; i < 9; i++) { v[i] = __expf(v[i] - m); s += v[i]; }
    s = block_sum256(s, red);

    const float inv = 1.0f / s;
    #pragma unroll
    for (int i = 0; i < 9; i++) p[tid + i * 256] = v[i] * inv;
}

// ======================================================================
// Kernel 4: xout[b] = attn[b] @ xin[b]    M=2304, N=768, K=2304 per batch
// 128x128 block tile, 8x8 micro, K-tile 16, f32x2 packed accumulators.
// Global->register prefetch double-buffer hides LDG latency under compute.
// ======================================================================
__global__ void __launch_bounds__(256, 2)
gemm_av_kernel(const float* __restrict__ attn, const float* __restrict__ xin,
               float* __restrict__ xout)
{
    const int b  = blockIdx.z;
    const float* A  = attn + (size_t)b * Nn * Nn;
    const float* Bm = xin  + (size_t)b * Nn * Dd;
    float*       C  = xout + (size_t)b * Nn * Dd;
    const int m0 = blockIdx.y * 128;
    const int n0 = blockIdx.x * 128;

    __shared__ float As[16][132];   // [k][m], pad 132 (16B-aligned rows)
    __shared__ float Bs[16][128];   // [k][n]

    const int tid = threadIdx.x;
    const int ty = tid >> 4, tx = tid & 15;

    // per-thread load coords (fixed across K-steps)
    const int am[2] = { (tid + 0)   >> 2, (tid + 256) >> 2 };
    const int ak[2] = { (tid + 0)   & 3,  (tid + 256) & 3  };
    const int bk[2] = { (tid + 0)   >> 5, (tid + 256) >> 5 };
    const int bn[2] = { (tid + 0)   & 31, (tid + 256) & 31 };

    unsigned long long c2[8][4];
    #pragma unroll
    for (int i = 0; i < 8; i++)
        #pragma unroll
        for (int j = 0; j < 4; j++) c2[i][j] = 0ULL;

    float4 pa[2], pb[2];
    // prefetch k-tile 0
    #pragma unroll
    for (int it = 0; it < 2; it++) {
        pa[it] = *(const float4*)&A[(size_t)(m0 + am[it]) * Nn + ak[it] * 4];
        pb[it] = *(const float4*)&Bm[(size_t)bk[it] * Dd + n0 + bn[it] * 4];
    }

    for (int k0 = 0; k0 < Nn; k0 += 16) {
        // commit prefetched tile to smem
        #pragma unroll
        for (int it = 0; it < 2; it++) {
            As[ak[it] * 4 + 0][am[it]] = pa[it].x;
            As[ak[it] * 4 + 1][am[it]] = pa[it].y;
            As[ak[it] * 4 + 2][am[it]] = pa[it].z;
            As[ak[it] * 4 + 3][am[it]] = pa[it].w;
            *(float4*)&Bs[bk[it]][bn[it] * 4] = pb[it];
        }
        __syncthreads();

        // issue next tile's loads (consumed after the trailing barrier)
        if (k0 + 16 < Nn) {
            const int kn = k0 + 16;
            #pragma unroll
            for (int it = 0; it < 2; it++) {
                pa[it] = *(const float4*)&A[(size_t)(m0 + am[it]) * Nn + kn + ak[it] * 4];
                pb[it] = *(const float4*)&Bm[(size_t)(kn + bk[it]) * Dd + n0 + bn[it] * 4];
            }
        }

        #pragma unroll
        for (int k = 0; k < 16; k++) {
            float4 a0 = *(const float4*)&As[k][ty * 8];
            float4 a1 = *(const float4*)&As[k][ty * 8 + 4];
            float4 b0 = *(const float4*)&Bs[k][tx * 8];
            float4 b1 = *(const float4*)&Bs[k][tx * 8 + 4];
            unsigned long long bb[4];
            PACK2(bb[0], b0.x, b0.y);
            PACK2(bb[1], b0.z, b0.w);
            PACK2(bb[2], b1.x, b1.y);
            PACK2(bb[3], b1.z, b1.w);
            float av[8] = {a0.x, a0.y, a0.z, a0.w, a1.x, a1.y, a1.z, a1.w};
            #pragma unroll
            for (int i = 0; i < 8; i++) {
                unsigned long long aa;
                PACK2(aa, av[i], av[i]);
                #pragma unroll
                for (int j = 0; j < 4; j++) FMA2(c2[i][j], aa, bb[j]);
            }
        }
        __syncthreads();
    }

    #pragma unroll
    for (int i = 0; i < 8; i++) {
        float2 p0 = *(float2*)&c2[i][0];
        float2 p1 = *(float2*)&c2[i][1];
        float2 p2 = *(float2*)&c2[i][2];
        float2 p3 = *(float2*)&c2[i][3];
        float4 o0 = make_float4(p0.x, p0.y, p1.x, p1.y);
        float4 o1 = make_float4(p2.x, p2.y, p3.x, p3.y);
        float* cp = &C[(size_t)(m0 + ty * 8 + i) * Dd + n0 + tx * 8];
        *(float4*)cp = o0;
        *((float4*)cp + 1) = o1;
    }
}

// ======================================================================
// Kernel 5: layernorm over last dim (768). One block per row.
// ======================================================================
__global__ void __launch_bounds__(256)
ln_kernel(const float* __restrict__ xin, const float* __restrict__ gamma,
          const float* __restrict__ beta, float* __restrict__ xout)
{
    __shared__ float red[8];
    const size_t row = blockIdx.x;
    const float* p = xin + row * (size_t)Dd;
    float* o = xout + row * (size_t)Dd;
    const int tid = threadIdx.x;

    float v[3];
    #pragma unroll
    for (int i = 0; i < 3; i++) v[i] = p[tid + i * 256];

    float s = v[0] + v[1] + v[2];
    s = block_sum256(s, red);
    const float mu = s * (1.0f / Dd);

    float d2 = 0.0f;
    #pragma unroll
    for (int i = 0; i < 3; i++) { float d = v[i] - mu; d2 += d * d; }
    d2 = block_sum256(d2, red);
    const float rs = rsqrtf(d2 * (1.0f / Dd) + LN_EPS);

    #pragma unroll
    for (int i = 0; i < 3; i++) {
        int c = tid + i * 256;
        o[c] = (v[i] - mu) * rs * gamma[c] + beta[c];
    }
}

// ======================================================================
// launch
// ======================================================================
extern "C" void kernel_launch(void* const* d_in, const int* in_sizes, int n_in,
                              void* d_out, int out_size)
{
    (void)in_sizes; (void)n_in; (void)out_size;
    const float* x     = (const float*)d_in[0];
    const float* Wq    = (const float*)d_in[1];
    const float* bq    = (const float*)d_in[2];
    const float* gamma = (const float*)d_in[3];
    const float* beta  = (const float*)d_in[4];
    float* out = (float*)d_out;

    float *qb, *simb, *xa, *xt;
    cudaGetSymbolAddress((void**)&qb,   g_q);
    cudaGetSymbolAddress((void**)&simb, g_sim);
    cudaGetSymbolAddress((void**)&xa,   g_xA);
    cudaGetSymbolAddress((void**)&xt,   g_xT);

    const int rows = Bn * Nn;                 // 18432
    const float* xin = x;
    float* lnout[3] = { xa, xa, out };

    for (int l = 0; l < 3; l++) {
        qproj_kernel  <<< rows / 64, 256 >>>(xin, Wq, bq, qb);
        sim_kernel    <<< dim3(Nn / 64, Nn / 64, Bn), 256 >>>(qb, simb);
        softmax_kernel<<< rows, 256 >>>(simb);
        gemm_av_kernel<<< dim3(Dd / 128, Nn / 128, Bn), 256 >>>(simb, xin, xt);
        ln_kernel     <<< rows, 256 >>>(xt, gamma, beta, lnout[l]);
        xin = lnout[l];
    }
}

// round 9
// speedup vs baseline: 1.7043x; 1.7043x over previous
#include <cuda_runtime.h>
#include <cuda_bf16.h>
#include <cstdint>
#include <cstddef>

// ---------------- problem constants ----------------
#define Bn 8
#define Nn 2304
#define Dd 768
#define Dm 64
#define K_SCALE 0.125f          // Dm^-0.5
#define LN_EPS 1e-5f

// ---------------- scratch (static device globals; no allocation) ----------------
__device__ float g_q[(size_t)Bn * Nn * Dm];                  // 4.7 MB
__device__ float g_sim[(size_t)Bn * Nn * Nn];                // 170 MB (pre-softmax)
__device__ __nv_bfloat16 g_ah[(size_t)Bn * Nn * Nn];         // 85 MB attn hi
__device__ __nv_bfloat16 g_al[(size_t)Bn * Nn * Nn];         // 85 MB attn lo
__device__ __nv_bfloat16 g_xth[(size_t)Bn * Dd * Nn];        // 28 MB x^T hi
__device__ __nv_bfloat16 g_xtl[(size_t)Bn * Dd * Nn];        // 28 MB x^T lo
__device__ float g_xA[(size_t)Bn * Nn * Dd];                 // post-LN ping
__device__ float g_xT[(size_t)Bn * Nn * Dd];                 // pre-LN temp

// ---------------- packed fp32x2 helpers ----------------
#define PACK2(d, lo, hi) asm("mov.b64 %0, {%1, %2};" : "=l"(d) : "f"(lo), "f"(hi))
#define FMA2(acc, a, b)  asm("fma.rn.f32x2 %0, %1, %2, %0;" : "+l"(acc) : "l"(a), "l"(b))

// ---------------- base-target tensor-core helpers (sm_80+ PTX, no tcgen05) ----
__device__ __forceinline__ uint32_t smem_u32(const void* p) {
    uint32_t r;
    asm("{ .reg .u64 t; cvta.to.shared.u64 t, %1; cvt.u32.u64 %0, t; }"
        : "=r"(r) : "l"(p));
    return r;
}

__device__ __forceinline__ void cp16(uint32_t dst, const void* src) {
    asm volatile("cp.async.cg.shared.global [%0], [%1], 16;"
                 :: "r"(dst), "l"(src) : "memory");
}
#define CP_COMMIT() asm volatile("cp.async.commit_group;" ::: "memory")
#define CP_WAIT(n)  asm volatile("cp.async.wait_group %0;" :: "n"(n) : "memory")

#define LDM_X4(r, addr) \
    asm volatile("ldmatrix.sync.aligned.m8n8.x4.shared.b16 {%0,%1,%2,%3}, [%4];" \
        : "=r"((r)[0]), "=r"((r)[1]), "=r"((r)[2]), "=r"((r)[3]) : "r"(addr))

#define MMA_BF16(c, a, b) \
    asm volatile("mma.sync.aligned.m16n8k16.row.col.f32.bf16.bf16.f32 " \
        "{%0,%1,%2,%3}, {%4,%5,%6,%7}, {%8,%9}, {%0,%1,%2,%3};" \
        : "+f"((c)[0]), "+f"((c)[1]), "+f"((c)[2]), "+f"((c)[3]) \
        : "r"((a)[0]), "r"((a)[1]), "r"((a)[2]), "r"((a)[3]), \
          "r"((b)[0]), "r"((b)[1]))

// ---------------- block reductions ----------------
__device__ __forceinline__ float block_sum256(float v, float* red) {
    #pragma unroll
    for (int o = 16; o; o >>= 1) v += __shfl_xor_sync(0xffffffffu, v, o);
    int tid = threadIdx.x;
    if ((tid & 31) == 0) red[tid >> 5] = v;
    __syncthreads();
    float t = red[0];
    #pragma unroll
    for (int w = 1; w < 8; w++) t += red[w];
    __syncthreads();
    return t;
}

__device__ __forceinline__ float block_max256(float v, float* red) {
    #pragma unroll
    for (int o = 16; o; o >>= 1) v = fmaxf(v, __shfl_xor_sync(0xffffffffu, v, o));
    int tid = threadIdx.x;
    if ((tid & 31) == 0) red[tid >> 5] = v;
    __syncthreads();
    float t = red[0];
    #pragma unroll
    for (int w = 1; w < 8; w++) t = fmaxf(t, red[w]);
    __syncthreads();
    return t;
}

// ======================================================================
// Kernel 1: q = x @ Wq + bq
// ======================================================================
__global__ void __launch_bounds__(256)
qproj_kernel(const float* __restrict__ x, const float* __restrict__ Wq,
             const float* __restrict__ bq, float* __restrict__ q)
{
    __shared__ float As[64][32];
    __shared__ float Bs[32][64];
    const int tid = threadIdx.x;
    const int m0  = blockIdx.x * 64;
    const int ty  = tid >> 4, tx = tid & 15;

    float acc[4][4];
    #pragma unroll
    for (int i = 0; i < 4; i++)
        #pragma unroll
        for (int j = 0; j < 4; j++) acc[i][j] = 0.0f;

    for (int kt = 0; kt < Dd; kt += 32) {
        #pragma unroll
        for (int it = 0; it < 8; it++) {
            int idx = tid + it * 256;
            int m = idx >> 5, k = idx & 31;
            As[m][k] = x[(size_t)(m0 + m) * Dd + kt + k];
        }
        #pragma unroll
        for (int it = 0; it < 8; it++) {
            int idx = tid + it * 256;
            int k = idx >> 6, n = idx & 63;
            Bs[k][n] = Wq[(size_t)(kt + k) * Dm + n];
        }
        __syncthreads();
        #pragma unroll
        for (int k = 0; k < 32; k++) {
            float a[4], b[4];
            #pragma unroll
            for (int i = 0; i < 4; i++) a[i] = As[ty * 4 + i][k];
            #pragma unroll
            for (int j = 0; j < 4; j++) b[j] = Bs[k][tx * 4 + j];
            #pragma unroll
            for (int i = 0; i < 4; i++)
                #pragma unroll
                for (int j = 0; j < 4; j++) acc[i][j] = fmaf(a[i], b[j], acc[i][j]);
        }
        __syncthreads();
    }
    #pragma unroll
    for (int i = 0; i < 4; i++)
        #pragma unroll
        for (int j = 0; j < 4; j++)
            q[(size_t)(m0 + ty * 4 + i) * Dm + tx * 4 + j] = acc[i][j] + bq[tx * 4 + j];
}

// ======================================================================
// Kernel 2: sim = scale * q @ q^T   (FFMA2 path)
// ======================================================================
__global__ void __launch_bounds__(256)
sim_kernel(const float* __restrict__ q, float* __restrict__ sim)
{
    const int b  = blockIdx.z;
    const int i0 = blockIdx.y * 64;
    const int j0 = blockIdx.x * 64;
    const float* Q = q + (size_t)b * Nn * Dm;

    __shared__ float Qi[64][65];
    __shared__ float Qj[64][65];

    const int tid = threadIdx.x;
    const int ty = tid >> 4, tx = tid & 15;

    #pragma unroll
    for (int it = 0; it < 4; it++) {
        int idx = tid + it * 256;
        int m = idx >> 4, k4 = idx & 15;
        float4 vi = *(const float4*)&Q[(size_t)(i0 + m) * Dm + k4 * 4];
        float4 vj = *(const float4*)&Q[(size_t)(j0 + m) * Dm + k4 * 4];
        Qi[m][k4 * 4 + 0] = vi.x; Qi[m][k4 * 4 + 1] = vi.y;
        Qi[m][k4 * 4 + 2] = vi.z; Qi[m][k4 * 4 + 3] = vi.w;
        Qj[m][k4 * 4 + 0] = vj.x; Qj[m][k4 * 4 + 1] = vj.y;
        Qj[m][k4 * 4 + 2] = vj.z; Qj[m][k4 * 4 + 3] = vj.w;
    }
    __syncthreads();

    unsigned long long c2[4][2];
    #pragma unroll
    for (int i = 0; i < 4; i++) { c2[i][0] = 0ULL; c2[i][1] = 0ULL; }

    #pragma unroll
    for (int k = 0; k < 64; k++) {
        float a[4], bv[4];
        #pragma unroll
        for (int i = 0; i < 4; i++) a[i]  = Qi[ty * 4 + i][k];
        #pragma unroll
        for (int j = 0; j < 4; j++) bv[j] = Qj[tx * 4 + j][k];
        unsigned long long bb0, bb1;
        PACK2(bb0, bv[0], bv[1]);
        PACK2(bb1, bv[2], bv[3]);
        #pragma unroll
        for (int i = 0; i < 4; i++) {
            unsigned long long aa;
            PACK2(aa, a[i], a[i]);
            FMA2(c2[i][0], aa, bb0);
            FMA2(c2[i][1], aa, bb1);
        }
    }

    float* S = sim + (size_t)b * Nn * Nn;
    #pragma unroll
    for (int i = 0; i < 4; i++) {
        float2 p0 = *(float2*)&c2[i][0];
        float2 p1 = *(float2*)&c2[i][1];
        float4 o = make_float4(p0.x * K_SCALE, p0.y * K_SCALE,
                               p1.x * K_SCALE, p1.y * K_SCALE);
        *(float4*)&S[(size_t)(i0 + ty * 4 + i) * Nn + j0 + tx * 4] = o;
    }
}

// ======================================================================
// Kernel 3: softmax + bf16 hi/lo split write. One block per row.
// ======================================================================
__global__ void __launch_bounds__(256)
softmax_split_kernel(const float* __restrict__ sim,
                     __nv_bfloat16* __restrict__ ah,
                     __nv_bfloat16* __restrict__ al)
{
    __shared__ float red[8];
    const size_t row = blockIdx.x;
    const float* p = sim + row * (size_t)Nn;
    const int tid = threadIdx.x;

    float v[9];
    #pragma unroll
    for (int i = 0; i < 9; i++) v[i] = p[tid + i * 256];

    float m = -3.0e38f;
    #pragma unroll
    for (int i = 0; i < 9; i++) m = fmaxf(m, v[i]);
    m = block_max256(m, red);

    float s = 0.0f;
    #pragma unroll
    for (int i = 0; i < 9; i++) { v[i] = __expf(v[i] - m); s += v[i]; }
    s = block_sum256(s, red);

    const float inv = 1.0f / s;
    #pragma unroll
    for (int i = 0; i < 9; i++) {
        float val = v[i] * inv;
        __nv_bfloat16 h = __float2bfloat16(val);
        __nv_bfloat16 l = __float2bfloat16(val - __bfloat162float(h));
        size_t o = row * (size_t)Nn + tid + i * 256;
        ah[o] = h;
        al[o] = l;
    }
}

// ======================================================================
// Kernel 3b: transpose + bf16 hi/lo split of x: [B,N,D] -> [B,D,N]
// ======================================================================
__global__ void __launch_bounds__(256)
xsplitT_kernel(const float* __restrict__ x,
               __nv_bfloat16* __restrict__ xth, __nv_bfloat16* __restrict__ xtl)
{
    __shared__ float tile[32][33];
    const int b = blockIdx.z;
    const int tok0 = blockIdx.x * 32;
    const int d0   = blockIdx.y * 32;
    const int tx = threadIdx.x & 31;
    const int ty = threadIdx.x >> 5;       // 0..7

    const float* xb = x + (size_t)b * Nn * Dd;
    #pragma unroll
    for (int i = 0; i < 4; i++)
        tile[ty + i * 8][tx] = xb[(size_t)(tok0 + ty + i * 8) * Dd + d0 + tx];
    __syncthreads();

    #pragma unroll
    for (int i = 0; i < 4; i++) {
        float v = tile[tx][ty + i * 8];
        __nv_bfloat16 h = __float2bfloat16(v);
        __nv_bfloat16 l = __float2bfloat16(v - __bfloat162float(h));
        size_t o = (size_t)b * Dd * Nn + (size_t)(d0 + ty + i * 8) * Nn + tok0 + tx;
        xth[o] = h;
        xtl[o] = l;
    }
}

// ======================================================================
// Kernel 4: mma.sync bf16 split GEMM: C = attn @ x
//   A = attn hi/lo  [m][k] k-contig (row-major)  -> ldmatrix non-trans
//   B = x^T  hi/lo  [n][k] k-contig (col-major)  -> ldmatrix non-trans
//   CTA 128x128, 8 warps 2(m)x4(n), warp tile 64x32, K-chunk 32,
//   cp.async double-buffered smem, 80B padded rows (conflict-free ldmatrix).
// ======================================================================
#define AROW 80                       // bytes per padded row (40 halves)
#define ARR_BYTES (128 * AROW)        // 10240
#define STAGE_BYTES (4 * ARR_BYTES)   // 40960  (Ah, Al, Bh, Bl)
#define GEMM_SMEM (2 * STAGE_BYTES)   // 81920
#define NCHUNK (Nn / 32)              // 72

__global__ void __launch_bounds__(256)
gemm_av_mma_kernel(const __nv_bfloat16* __restrict__ Ah,
                   const __nv_bfloat16* __restrict__ Al,
                   const __nv_bfloat16* __restrict__ Bh,
                   const __nv_bfloat16* __restrict__ Bl,
                   float* __restrict__ C)
{
    extern __shared__ __align__(128) char dsm[];

    const int tid  = threadIdx.x;
    const int wid  = tid >> 5;
    const int lane = tid & 31;
    const int warp_m = wid >> 2;          // 0..1
    const int warp_n = wid & 3;           // 0..3
    const int b  = blockIdx.z;
    const int n0 = blockIdx.x * 128;
    const int m0 = blockIdx.y * 128;

    const uint32_t sbase = smem_u32(dsm);

    const __nv_bfloat16* Ah_b = Ah + (size_t)b * Nn * Nn;
    const __nv_bfloat16* Al_b = Al + (size_t)b * Nn * Nn;
    const __nv_bfloat16* Bh_b = Bh + (size_t)b * Dd * Nn;
    const __nv_bfloat16* Bl_b = Bl + (size_t)b * Dd * Nn;

    // per-thread fill coords: 2048 16B-chunks per stage, 8 per thread
    // idx: arr = idx>>9 (0:Ah 1:Al 2:Bh 3:Bl), r = (idx>>2)&127, j = idx&3
    const __nv_bfloat16* src_row[8];
    uint32_t dst_off[8];
    #pragma unroll
    for (int t = 0; t < 8; t++) {
        int idx = tid + t * 256;
        int arr = idx >> 9;
        int r   = (idx >> 2) & 127;
        int j   = idx & 3;
        const __nv_bfloat16* base =
            (arr == 0) ? Ah_b : (arr == 1) ? Al_b : (arr == 2) ? Bh_b : Bl_b;
        int grow = (arr < 2) ? (m0 + r) : (n0 + r);
        src_row[t] = base + (size_t)grow * Nn + j * 8;
        dst_off[t] = (uint32_t)(arr * ARR_BYTES + r * AROW + j * 16);
    }

    float acc[4][4][4];
    #pragma unroll
    for (int mi = 0; mi < 4; mi++)
        #pragma unroll
        for (int ni = 0; ni < 4; ni++)
            #pragma unroll
            for (int k = 0; k < 4; k++) acc[mi][ni][k] = 0.0f;

    // prologue: fill stage 0 (k0 = 0)
    #pragma unroll
    for (int t = 0; t < 8; t++) cp16(sbase + dst_off[t], src_row[t]);
    CP_COMMIT();

    const int tq  = lane >> 3;            // ldmatrix tile index 0..3
    const int i7  = lane & 7;
    // A: row offset within tile group = (tq&1)*8 + i7, k-byte = (tq>>1)*16
    const uint32_t a_row = (uint32_t)(warp_m * 64 + ((tq & 1) << 3) + i7);
    const uint32_t a_kb  = (uint32_t)((tq >> 1) << 4);
    // B: n offset = (tq>>1)*8 + i7, k-byte = (tq&1)*16
    const uint32_t b_row = (uint32_t)(warp_n * 32 + ((tq >> 1) << 3) + i7);
    const uint32_t b_kb  = (uint32_t)((tq & 1) << 4);

    for (int c = 0; c < NCHUNK; c++) {
        if (c + 1 < NCHUNK) {
            const int k0 = (c + 1) * 32;
            const uint32_t sdst = sbase + ((c + 1) & 1) * STAGE_BYTES;
            #pragma unroll
            for (int t = 0; t < 8; t++) cp16(sdst + dst_off[t], src_row[t] + k0);
            CP_COMMIT();
            CP_WAIT(1);
        } else {
            CP_WAIT(0);
        }
        __syncthreads();

        const uint32_t sb = sbase + (c & 1) * STAGE_BYTES;

        #pragma unroll
        for (int ks = 0; ks < 2; ks++) {
            const uint32_t koff = (uint32_t)(ks * 32);   // 16 halves = 32 bytes

            uint32_t ah_f[4][4], al_f[4][4];
            uint32_t bh_f[4][2], bl_f[4][2];

            #pragma unroll
            for (int mi = 0; mi < 4; mi++) {
                uint32_t addr = sb + (a_row + mi * 16) * AROW + koff + a_kb;
                LDM_X4(ah_f[mi], addr);
                LDM_X4(al_f[mi], addr + ARR_BYTES);
            }
            #pragma unroll
            for (int nj = 0; nj < 2; nj++) {
                uint32_t addr = sb + 2 * ARR_BYTES + (b_row + nj * 16) * AROW + koff + b_kb;
                uint32_t r[4];
                LDM_X4(r, addr);
                bh_f[nj * 2][0] = r[0]; bh_f[nj * 2][1] = r[1];
                bh_f[nj * 2 + 1][0] = r[2]; bh_f[nj * 2 + 1][1] = r[3];
                LDM_X4(r, addr + ARR_BYTES);
                bl_f[nj * 2][0] = r[0]; bl_f[nj * 2][1] = r[1];
                bl_f[nj * 2 + 1][0] = r[2]; bl_f[nj * 2 + 1][1] = r[3];
            }

            #pragma unroll
            for (int mi = 0; mi < 4; mi++)
                #pragma unroll
                for (int ni = 0; ni < 4; ni++) {
                    MMA_BF16(acc[mi][ni], ah_f[mi], bh_f[ni]);
                    MMA_BF16(acc[mi][ni], ah_f[mi], bl_f[ni]);
                    MMA_BF16(acc[mi][ni], al_f[mi], bh_f[ni]);
                }
        }
        __syncthreads();
    }

    // epilogue: acc frag (m16n8): d0,d1 = row g cols 2t,2t+1 ; d2,d3 = row g+8
    const int g  = lane >> 2;
    const int t2 = (lane & 3) * 2;
    float* Cb = C + (size_t)b * Nn * Dd;
    #pragma unroll
    for (int mi = 0; mi < 4; mi++) {
        const int row0 = m0 + warp_m * 64 + mi * 16 + g;
        #pragma unroll
        for (int ni = 0; ni < 4; ni++) {
            const int col = n0 + warp_n * 32 + ni * 8 + t2;
            *(float2*)&Cb[(size_t)row0 * Dd + col] =
                make_float2(acc[mi][ni][0], acc[mi][ni][1]);
            *(float2*)&Cb[(size_t)(row0 + 8) * Dd + col] =
                make_float2(acc[mi][ni][2], acc[mi][ni][3]);
        }
    }
}

// ======================================================================
// Kernel 5: layernorm over last dim (768). One block per row.
// ======================================================================
__global__ void __launch_bounds__(256)
ln_kernel(const float* __restrict__ xin, const float* __restrict__ gamma,
          const float* __restrict__ beta, float* __restrict__ xout)
{
    __shared__ float red[8];
    const size_t row = blockIdx.x;
    const float* p = xin + row * (size_t)Dd;
    float* o = xout + row * (size_t)Dd;
    const int tid = threadIdx.x;

    float v[3];
    #pragma unroll
    for (int i = 0; i < 3; i++) v[i] = p[tid + i * 256];

    float s = v[0] + v[1] + v[2];
    s = block_sum256(s, red);
    const float mu = s * (1.0f / Dd);

    float d2 = 0.0f;
    #pragma unroll
    for (int i = 0; i < 3; i++) { float d = v[i] - mu; d2 += d * d; }
    d2 = block_sum256(d2, red);
    const float rs = rsqrtf(d2 * (1.0f / Dd) + LN_EPS);

    #pragma unroll
    for (int i = 0; i < 3; i++) {
        int c = tid + i * 256;
        o[c] = (v[i] - mu) * rs * gamma[c] + beta[c];
    }
}

// ======================================================================
// launch
// ======================================================================
extern "C" void kernel_launch(void* const* d_in, const int* in_sizes, int n_in,
                              void* d_out, int out_size)
{
    (void)in_sizes; (void)n_in; (void)out_size;
    const float* x     = (const float*)d_in[0];
    const float* Wq    = (const float*)d_in[1];
    const float* bq    = (const float*)d_in[2];
    const float* gamma = (const float*)d_in[3];
    const float* beta  = (const float*)d_in[4];
    float* out = (float*)d_out;

    float *qb, *simb, *xa, *xt;
    __nv_bfloat16 *ah, *al, *xth, *xtl;
    cudaGetSymbolAddress((void**)&qb,   g_q);
    cudaGetSymbolAddress((void**)&simb, g_sim);
    cudaGetSymbolAddress((void**)&ah,   g_ah);
    cudaGetSymbolAddress((void**)&al,   g_al);
    cudaGetSymbolAddress((void**)&xth,  g_xth);
    cudaGetSymbolAddress((void**)&xtl,  g_xtl);
    cudaGetSymbolAddress((void**)&xa,   g_xA);
    cudaGetSymbolAddress((void**)&xt,   g_xT);

    cudaFuncSetAttribute(gemm_av_mma_kernel,
                         cudaFuncAttributeMaxDynamicSharedMemorySize, GEMM_SMEM);

    const int rows = Bn * Nn;                 // 18432
    const float* xin = x;
    float* lnout[3] = { xa, xa, out };

    for (int l = 0; l < 3; l++) {
        qproj_kernel        <<< rows / 64, 256 >>>(xin, Wq, bq, qb);
        sim_kernel          <<< dim3(Nn / 64, Nn / 64, Bn), 256 >>>(qb, simb);
        softmax_split_kernel<<< rows, 256 >>>(simb, ah, al);
        xsplitT_kernel      <<< dim3(Nn / 32, Dd / 32, Bn), 256 >>>(xin, xth, xtl);
        gemm_av_mma_kernel  <<< dim3(Dd / 128, Nn / 128, Bn), 256, GEMM_SMEM >>>
                                (ah, al, xth, xtl, xt);
        ln_kernel           <<< rows, 256 >>>(xt, gamma, beta, lnout[l]);
        xin = lnout[l];
    }
}

// round 10
// speedup vs baseline: 1.9365x; 1.1362x over previous
#include <cuda_runtime.h>
#include <cuda_bf16.h>
#include <cstdint>
#include <cstddef>

// ---------------- problem constants ----------------
#define Bn 8
#define Nn 2304
#define Dd 768
#define Dm 64
#define K_SCALE 0.125f          // Dm^-0.5
#define LN_EPS 1e-5f

// ---------------- scratch (static device globals; no allocation) ----------------
__device__ float g_sim[(size_t)Bn * Nn * Nn];                // 170 MB (pre-softmax)
__device__ __nv_bfloat16 g_qh[(size_t)Bn * Nn * Dm];         // 2.4 MB q hi
__device__ __nv_bfloat16 g_ql[(size_t)Bn * Nn * Dm];         // 2.4 MB q lo
__device__ __nv_bfloat16 g_ah[(size_t)Bn * Nn * Nn];         // 85 MB attn hi
__device__ __nv_bfloat16 g_al[(size_t)Bn * Nn * Nn];         // 85 MB attn lo
__device__ __nv_bfloat16 g_xth[(size_t)Bn * Dd * Nn];        // 28 MB x^T hi
__device__ __nv_bfloat16 g_xtl[(size_t)Bn * Dd * Nn];        // 28 MB x^T lo
__device__ float g_xA[(size_t)Bn * Nn * Dd];                 // post-LN ping
__device__ float g_xT[(size_t)Bn * Nn * Dd];                 // pre-LN temp

// ---------------- base-target tensor-core helpers (sm_80+ PTX) ----------------
__device__ __forceinline__ uint32_t smem_u32(const void* p) {
    uint32_t r;
    asm("{ .reg .u64 t; cvta.to.shared.u64 t, %1; cvt.u32.u64 %0, t; }"
        : "=r"(r) : "l"(p));
    return r;
}

__device__ __forceinline__ void cp16(uint32_t dst, const void* src) {
    asm volatile("cp.async.cg.shared.global [%0], [%1], 16;"
                 :: "r"(dst), "l"(src) : "memory");
}
#define CP_COMMIT() asm volatile("cp.async.commit_group;" ::: "memory")
#define CP_WAIT(n)  asm volatile("cp.async.wait_group %0;" :: "n"(n) : "memory")

#define LDM_X4(r, addr) \
    asm volatile("ldmatrix.sync.aligned.m8n8.x4.shared.b16 {%0,%1,%2,%3}, [%4];" \
        : "=r"((r)[0]), "=r"((r)[1]), "=r"((r)[2]), "=r"((r)[3]) : "r"(addr))

#define MMA_BF16(c, a, b) \
    asm volatile("mma.sync.aligned.m16n8k16.row.col.f32.bf16.bf16.f32 " \
        "{%0,%1,%2,%3}, {%4,%5,%6,%7}, {%8,%9}, {%0,%1,%2,%3};" \
        : "+f"((c)[0]), "+f"((c)[1]), "+f"((c)[2]), "+f"((c)[3]) \
        : "r"((a)[0]), "r"((a)[1]), "r"((a)[2]), "r"((a)[3]), \
          "r"((b)[0]), "r"((b)[1]))

// ---------------- block reductions ----------------
__device__ __forceinline__ float block_sum256(float v, float* red) {
    #pragma unroll
    for (int o = 16; o; o >>= 1) v += __shfl_xor_sync(0xffffffffu, v, o);
    int tid = threadIdx.x;
    if ((tid & 31) == 0) red[tid >> 5] = v;
    __syncthreads();
    float t = red[0];
    #pragma unroll
    for (int w = 1; w < 8; w++) t += red[w];
    __syncthreads();
    return t;
}

__device__ __forceinline__ float block_max256(float v, float* red) {
    #pragma unroll
    for (int o = 16; o; o >>= 1) v = fmaxf(v, __shfl_xor_sync(0xffffffffu, v, o));
    int tid = threadIdx.x;
    if ((tid & 31) == 0) red[tid >> 5] = v;
    __syncthreads();
    float t = red[0];
    #pragma unroll
    for (int w = 1; w < 8; w++) t = fmaxf(t, red[w]);
    __syncthreads();
    return t;
}

// ======================================================================
// Kernel 1: q = x @ Wq + bq, written as bf16 hi/lo split
// ======================================================================
__global__ void __launch_bounds__(256)
qproj_kernel(const float* __restrict__ x, const float* __restrict__ Wq,
             const float* __restrict__ bq,
             __nv_bfloat16* __restrict__ qh, __nv_bfloat16* __restrict__ ql)
{
    __shared__ float As[64][32];
    __shared__ float Bs[32][64];
    const int tid = threadIdx.x;
    const int m0  = blockIdx.x * 64;
    const int ty  = tid >> 4, tx = tid & 15;

    float acc[4][4];
    #pragma unroll
    for (int i = 0; i < 4; i++)
        #pragma unroll
        for (int j = 0; j < 4; j++) acc[i][j] = 0.0f;

    for (int kt = 0; kt < Dd; kt += 32) {
        #pragma unroll
        for (int it = 0; it < 8; it++) {
            int idx = tid + it * 256;
            int m = idx >> 5, k = idx & 31;
            As[m][k] = x[(size_t)(m0 + m) * Dd + kt + k];
        }
        #pragma unroll
        for (int it = 0; it < 8; it++) {
            int idx = tid + it * 256;
            int k = idx >> 6, n = idx & 63;
            Bs[k][n] = Wq[(size_t)(kt + k) * Dm + n];
        }
        __syncthreads();
        #pragma unroll
        for (int k = 0; k < 32; k++) {
            float a[4], b[4];
            #pragma unroll
            for (int i = 0; i < 4; i++) a[i] = As[ty * 4 + i][k];
            #pragma unroll
            for (int j = 0; j < 4; j++) b[j] = Bs[k][tx * 4 + j];
            #pragma unroll
            for (int i = 0; i < 4; i++)
                #pragma unroll
                for (int j = 0; j < 4; j++) acc[i][j] = fmaf(a[i], b[j], acc[i][j]);
        }
        __syncthreads();
    }
    #pragma unroll
    for (int i = 0; i < 4; i++)
        #pragma unroll
        for (int j = 0; j < 4; j++) {
            float v = acc[i][j] + bq[tx * 4 + j];
            __nv_bfloat16 h = __float2bfloat16(v);
            __nv_bfloat16 l = __float2bfloat16(v - __bfloat162float(h));
            size_t o = (size_t)(m0 + ty * 4 + i) * Dm + tx * 4 + j;
            qh[o] = h;
            ql[o] = l;
        }
}

// ======================================================================
// Kernel 2: sim = scale * q @ q^T  via mma.sync bf16 3-term split.
//   CTA 128(i) x 128(j), K=64 single shot. 8 warps 2(m)x4(n).
//   smem: Qi_h, Qi_l, Qj_h, Qj_l, each 128 rows x 144B padded (64 bf16 used).
// ======================================================================
#define SROW 144
#define SARR (128 * SROW)           // 18432
#define SIM_SMEM (4 * SARR)         // 73728

__global__ void __launch_bounds__(256)
sim_mma_kernel(const __nv_bfloat16* __restrict__ qh,
               const __nv_bfloat16* __restrict__ ql,
               float* __restrict__ sim)
{
    extern __shared__ __align__(128) char dsm[];

    const int tid  = threadIdx.x;
    const int wid  = tid >> 5;
    const int lane = tid & 31;
    const int warp_m = wid >> 2;          // 0..1
    const int warp_n = wid & 3;           // 0..3
    const int b  = blockIdx.z;
    const int j0 = blockIdx.x * 128;
    const int i0 = blockIdx.y * 128;

    const uint32_t sbase = smem_u32(dsm);
    const __nv_bfloat16* qh_b = qh + (size_t)b * Nn * Dm;
    const __nv_bfloat16* ql_b = ql + (size_t)b * Nn * Dm;

    // fill: 4096 16B chunks, 16 per thread
    #pragma unroll
    for (int t = 0; t < 16; t++) {
        int idx = tid + t * 256;
        int arr = idx >> 10;              // 0:Qi_h 1:Qi_l 2:Qj_h 3:Qj_l
        int r   = (idx >> 3) & 127;
        int j   = idx & 7;
        const __nv_bfloat16* base = (arr == 0 || arr == 2) ? qh_b : ql_b;
        int grow = (arr < 2) ? (i0 + r) : (j0 + r);
        cp16(sbase + (uint32_t)(arr * SARR + r * SROW + j * 16),
             base + (size_t)grow * Dm + j * 8);
    }
    CP_COMMIT();
    CP_WAIT(0);
    __syncthreads();

    float acc[4][4][4];
    #pragma unroll
    for (int mi = 0; mi < 4; mi++)
        #pragma unroll
        for (int ni = 0; ni < 4; ni++)
            #pragma unroll
            for (int k = 0; k < 4; k++) acc[mi][ni][k] = 0.0f;

    const int tq = lane >> 3;
    const int i7 = lane & 7;
    const uint32_t a_row = (uint32_t)(warp_m * 64 + ((tq & 1) << 3) + i7);
    const uint32_t a_kb  = (uint32_t)((tq >> 1) << 4);
    const uint32_t b_row = (uint32_t)(warp_n * 32 + ((tq >> 1) << 3) + i7);
    const uint32_t b_kb  = (uint32_t)((tq & 1) << 4);

    #pragma unroll
    for (int ks = 0; ks < 4; ks++) {
        const uint32_t koff = (uint32_t)(ks * 32);

        uint32_t ah_f[4][4], al_f[4][4];
        uint32_t bh_f[4][2], bl_f[4][2];

        #pragma unroll
        for (int mi = 0; mi < 4; mi++) {
            uint32_t addr = sbase + (a_row + mi * 16) * SROW + koff + a_kb;
            LDM_X4(ah_f[mi], addr);
            LDM_X4(al_f[mi], addr + SARR);
        }
        #pragma unroll
        for (int nj = 0; nj < 2; nj++) {
            uint32_t addr = sbase + 2 * SARR + (b_row + nj * 16) * SROW + koff + b_kb;
            uint32_t r[4];
            LDM_X4(r, addr);
            bh_f[nj * 2][0] = r[0]; bh_f[nj * 2][1] = r[1];
            bh_f[nj * 2 + 1][0] = r[2]; bh_f[nj * 2 + 1][1] = r[3];
            LDM_X4(r, addr + SARR);
            bl_f[nj * 2][0] = r[0]; bl_f[nj * 2][1] = r[1];
            bl_f[nj * 2 + 1][0] = r[2]; bl_f[nj * 2 + 1][1] = r[3];
        }

        #pragma unroll
        for (int mi = 0; mi < 4; mi++)
            #pragma unroll
            for (int ni = 0; ni < 4; ni++) {
                MMA_BF16(acc[mi][ni], ah_f[mi], bh_f[ni]);
                MMA_BF16(acc[mi][ni], ah_f[mi], bl_f[ni]);
                MMA_BF16(acc[mi][ni], al_f[mi], bh_f[ni]);
            }
    }

    const int g  = lane >> 2;
    const int t2 = (lane & 3) * 2;
    float* S = sim + (size_t)b * Nn * Nn;
    #pragma unroll
    for (int mi = 0; mi < 4; mi++) {
        const int row0 = i0 + warp_m * 64 + mi * 16 + g;
        #pragma unroll
        for (int ni = 0; ni < 4; ni++) {
            const int col = j0 + warp_n * 32 + ni * 8 + t2;
            *(float2*)&S[(size_t)row0 * Nn + col] =
                make_float2(acc[mi][ni][0] * K_SCALE, acc[mi][ni][1] * K_SCALE);
            *(float2*)&S[(size_t)(row0 + 8) * Nn + col] =
                make_float2(acc[mi][ni][2] * K_SCALE, acc[mi][ni][3] * K_SCALE);
        }
    }
}

// ======================================================================
// Kernel 3: softmax + bf16 hi/lo split write. One block per row.
// ======================================================================
__global__ void __launch_bounds__(256)
softmax_split_kernel(const float* __restrict__ sim,
                     __nv_bfloat16* __restrict__ ah,
                     __nv_bfloat16* __restrict__ al)
{
    __shared__ float red[8];
    const size_t row = blockIdx.x;
    const float* p = sim + row * (size_t)Nn;
    const int tid = threadIdx.x;

    float v[9];
    #pragma unroll
    for (int i = 0; i < 9; i++) v[i] = p[tid + i * 256];

    float m = -3.0e38f;
    #pragma unroll
    for (int i = 0; i < 9; i++) m = fmaxf(m, v[i]);
    m = block_max256(m, red);

    float s = 0.0f;
    #pragma unroll
    for (int i = 0; i < 9; i++) { v[i] = __expf(v[i] - m); s += v[i]; }
    s = block_sum256(s, red);

    const float inv = 1.0f / s;
    #pragma unroll
    for (int i = 0; i < 9; i++) {
        float val = v[i] * inv;
        __nv_bfloat16 h = __float2bfloat16(val);
        __nv_bfloat16 l = __float2bfloat16(val - __bfloat162float(h));
        size_t o = row * (size_t)Nn + tid + i * 256;
        ah[o] = h;
        al[o] = l;
    }
}

// ======================================================================
// Kernel 3b: transpose + bf16 hi/lo split of x: [B,N,D] -> [B,D,N]
// ======================================================================
__global__ void __launch_bounds__(256)
xsplitT_kernel(const float* __restrict__ x,
               __nv_bfloat16* __restrict__ xth, __nv_bfloat16* __restrict__ xtl)
{
    __shared__ float tile[32][33];
    const int b = blockIdx.z;
    const int tok0 = blockIdx.x * 32;
    const int d0   = blockIdx.y * 32;
    const int tx = threadIdx.x & 31;
    const int ty = threadIdx.x >> 5;       // 0..7

    const float* xb = x + (size_t)b * Nn * Dd;
    #pragma unroll
    for (int i = 0; i < 4; i++)
        tile[ty + i * 8][tx] = xb[(size_t)(tok0 + ty + i * 8) * Dd + d0 + tx];
    __syncthreads();

    #pragma unroll
    for (int i = 0; i < 4; i++) {
        float v = tile[tx][ty + i * 8];
        __nv_bfloat16 h = __float2bfloat16(v);
        __nv_bfloat16 l = __float2bfloat16(v - __bfloat162float(h));
        size_t o = (size_t)b * Dd * Nn + (size_t)(d0 + ty + i * 8) * Nn + tok0 + tx;
        xth[o] = h;
        xtl[o] = l;
    }
}

// ======================================================================
// Kernel 4: mma.sync bf16 split GEMM: C = attn @ x  (unchanged, passing)
// ======================================================================
#define AROW 80
#define ARR_BYTES (128 * AROW)        // 10240
#define STAGE_BYTES (4 * ARR_BYTES)   // 40960
#define GEMM_SMEM (2 * STAGE_BYTES)   // 81920
#define NCHUNK (Nn / 32)              // 72

__global__ void __launch_bounds__(256)
gemm_av_mma_kernel(const __nv_bfloat16* __restrict__ Ah,
                   const __nv_bfloat16* __restrict__ Al,
                   const __nv_bfloat16* __restrict__ Bh,
                   const __nv_bfloat16* __restrict__ Bl,
                   float* __restrict__ C)
{
    extern __shared__ __align__(128) char dsm[];

    const int tid  = threadIdx.x;
    const int wid  = tid >> 5;
    const int lane = tid & 31;
    const int warp_m = wid >> 2;
    const int warp_n = wid & 3;
    const int b  = blockIdx.z;
    const int n0 = blockIdx.x * 128;
    const int m0 = blockIdx.y * 128;

    const uint32_t sbase = smem_u32(dsm);

    const __nv_bfloat16* Ah_b = Ah + (size_t)b * Nn * Nn;
    const __nv_bfloat16* Al_b = Al + (size_t)b * Nn * Nn;
    const __nv_bfloat16* Bh_b = Bh + (size_t)b * Dd * Nn;
    const __nv_bfloat16* Bl_b = Bl + (size_t)b * Dd * Nn;

    const __nv_bfloat16* src_row[8];
    uint32_t dst_off[8];
    #pragma unroll
    for (int t = 0; t < 8; t++) {
        int idx = tid + t * 256;
        int arr = idx >> 9;
        int r   = (idx >> 2) & 127;
        int j   = idx & 3;
        const __nv_bfloat16* base =
            (arr == 0) ? Ah_b : (arr == 1) ? Al_b : (arr == 2) ? Bh_b : Bl_b;
        int grow = (arr < 2) ? (m0 + r) : (n0 + r);
        src_row[t] = base + (size_t)grow * Nn + j * 8;
        dst_off[t] = (uint32_t)(arr * ARR_BYTES + r * AROW + j * 16);
    }

    float acc[4][4][4];
    #pragma unroll
    for (int mi = 0; mi < 4; mi++)
        #pragma unroll
        for (int ni = 0; ni < 4; ni++)
            #pragma unroll
            for (int k = 0; k < 4; k++) acc[mi][ni][k] = 0.0f;

    #pragma unroll
    for (int t = 0; t < 8; t++) cp16(sbase + dst_off[t], src_row[t]);
    CP_COMMIT();

    const int tq  = lane >> 3;
    const int i7  = lane & 7;
    const uint32_t a_row = (uint32_t)(warp_m * 64 + ((tq & 1) << 3) + i7);
    const uint32_t a_kb  = (uint32_t)((tq >> 1) << 4);
    const uint32_t b_row = (uint32_t)(warp_n * 32 + ((tq >> 1) << 3) + i7);
    const uint32_t b_kb  = (uint32_t)((tq & 1) << 4);

    for (int c = 0; c < NCHUNK; c++) {
        if (c + 1 < NCHUNK) {
            const int k0 = (c + 1) * 32;
            const uint32_t sdst = sbase + ((c + 1) & 1) * STAGE_BYTES;
            #pragma unroll
            for (int t = 0; t < 8; t++) cp16(sdst + dst_off[t], src_row[t] + k0);
            CP_COMMIT();
            CP_WAIT(1);
        } else {
            CP_WAIT(0);
        }
        __syncthreads();

        const uint32_t sb = sbase + (c & 1) * STAGE_BYTES;

        #pragma unroll
        for (int ks = 0; ks < 2; ks++) {
            const uint32_t koff = (uint32_t)(ks * 32);

            uint32_t ah_f[4][4], al_f[4][4];
            uint32_t bh_f[4][2], bl_f[4][2];

            #pragma unroll
            for (int mi = 0; mi < 4; mi++) {
                uint32_t addr = sb + (a_row + mi * 16) * AROW + koff + a_kb;
                LDM_X4(ah_f[mi], addr);
                LDM_X4(al_f[mi], addr + ARR_BYTES);
            }
            #pragma unroll
            for (int nj = 0; nj < 2; nj++) {
                uint32_t addr = sb + 2 * ARR_BYTES + (b_row + nj * 16) * AROW + koff + b_kb;
                uint32_t r[4];
                LDM_X4(r, addr);
                bh_f[nj * 2][0] = r[0]; bh_f[nj * 2][1] = r[1];
                bh_f[nj * 2 + 1][0] = r[2]; bh_f[nj * 2 + 1][1] = r[3];
                LDM_X4(r, addr + ARR_BYTES);
                bl_f[nj * 2][0] = r[0]; bl_f[nj * 2][1] = r[1];
                bl_f[nj * 2 + 1][0] = r[2]; bl_f[nj * 2 + 1][1] = r[3];
            }

            #pragma unroll
            for (int mi = 0; mi < 4; mi++)
                #pragma unroll
                for (int ni = 0; ni < 4; ni++) {
                    MMA_BF16(acc[mi][ni], ah_f[mi], bh_f[ni]);
                    MMA_BF16(acc[mi][ni], ah_f[mi], bl_f[ni]);
                    MMA_BF16(acc[mi][ni], al_f[mi], bh_f[ni]);
                }
        }
        __syncthreads();
    }

    const int g  = lane >> 2;
    const int t2 = (lane & 3) * 2;
    float* Cb = C + (size_t)b * Nn * Dd;
    #pragma unroll
    for (int mi = 0; mi < 4; mi++) {
        const int row0 = m0 + warp_m * 64 + mi * 16 + g;
        #pragma unroll
        for (int ni = 0; ni < 4; ni++) {
            const int col = n0 + warp_n * 32 + ni * 8 + t2;
            *(float2*)&Cb[(size_t)row0 * Dd + col] =
                make_float2(acc[mi][ni][0], acc[mi][ni][1]);
            *(float2*)&Cb[(size_t)(row0 + 8) * Dd + col] =
                make_float2(acc[mi][ni][2], acc[mi][ni][3]);
        }
    }
}

// ======================================================================
// Kernel 5: layernorm over last dim (768). One block per row.
// ======================================================================
__global__ void __launch_bounds__(256)
ln_kernel(const float* __restrict__ xin, const float* __restrict__ gamma,
          const float* __restrict__ beta, float* __restrict__ xout)
{
    __shared__ float red[8];
    const size_t row = blockIdx.x;
    const float* p = xin + row * (size_t)Dd;
    float* o = xout + row * (size_t)Dd;
    const int tid = threadIdx.x;

    float v[3];
    #pragma unroll
    for (int i = 0; i < 3; i++) v[i] = p[tid + i * 256];

    float s = v[0] + v[1] + v[2];
    s = block_sum256(s, red);
    const float mu = s * (1.0f / Dd);

    float d2 = 0.0f;
    #pragma unroll
    for (int i = 0; i < 3; i++) { float d = v[i] - mu; d2 += d * d; }
    d2 = block_sum256(d2, red);
    const float rs = rsqrtf(d2 * (1.0f / Dd) + LN_EPS);

    #pragma unroll
    for (int i = 0; i < 3; i++) {
        int c = tid + i * 256;
        o[c] = (v[i] - mu) * rs * gamma[c] + beta[c];
    }
}

// ======================================================================
// launch
// ======================================================================
extern "C" void kernel_launch(void* const* d_in, const int* in_sizes, int n_in,
                              void* d_out, int out_size)
{
    (void)in_sizes; (void)n_in; (void)out_size;
    const float* x     = (const float*)d_in[0];
    const float* Wq    = (const float*)d_in[1];
    const float* bq    = (const float*)d_in[2];
    const float* gamma = (const float*)d_in[3];
    const float* beta  = (const float*)d_in[4];
    float* out = (float*)d_out;

    float *simb, *xa, *xt;
    __nv_bfloat16 *qhp, *qlp, *ah, *al, *xth, *xtl;
    cudaGetSymbolAddress((void**)&simb, g_sim);
    cudaGetSymbolAddress((void**)&qhp,  g_qh);
    cudaGetSymbolAddress((void**)&qlp,  g_ql);
    cudaGetSymbolAddress((void**)&ah,   g_ah);
    cudaGetSymbolAddress((void**)&al,   g_al);
    cudaGetSymbolAddress((void**)&xth,  g_xth);
    cudaGetSymbolAddress((void**)&xtl,  g_xtl);
    cudaGetSymbolAddress((void**)&xa,   g_xA);
    cudaGetSymbolAddress((void**)&xt,   g_xT);

    cudaFuncSetAttribute(gemm_av_mma_kernel,
                         cudaFuncAttributeMaxDynamicSharedMemorySize, GEMM_SMEM);
    cudaFuncSetAttribute(sim_mma_kernel,
                         cudaFuncAttributeMaxDynamicSharedMemorySize, SIM_SMEM);

    const int rows = Bn * Nn;                 // 18432
    const float* xin = x;
    float* lnout[3] = { xa, xa, out };

    for (int l = 0; l < 3; l++) {
        qproj_kernel        <<< rows / 64, 256 >>>(xin, Wq, bq, qhp, qlp);
        sim_mma_kernel      <<< dim3(Nn / 128, Nn / 128, Bn), 256, SIM_SMEM >>>
                                (qhp, qlp, simb);
        softmax_split_kernel<<< rows, 256 >>>(simb, ah, al);
        xsplitT_kernel      <<< dim3(Nn / 32, Dd / 32, Bn), 256 >>>(xin, xth, xtl);
        gemm_av_mma_kernel  <<< dim3(Dd / 128, Nn / 128, Bn), 256, GEMM_SMEM >>>
                                (ah, al, xth, xtl, xt);
        ln_kernel           <<< rows, 256 >>>(xt, gamma, beta, lnout[l]);
        xin = lnout[l];
    }
}

// round 16
// speedup vs baseline: 1.9752x; 1.0200x over previous
#include <cuda_runtime.h>
#include <cuda_bf16.h>
#include <cstdint>
#include <cstddef>

// ---------------- problem constants ----------------
#define Bn 8
#define Nn 2304
#define Dd 768
#define Dm 64
#define K_SCALE 0.125f          // Dm^-0.5
#define LN_EPS 1e-5f

// ---------------- scratch (static device globals; no allocation) ----------------
__device__ __nv_bfloat16 g_qh[(size_t)Bn * Nn * Dm];         // 2.4 MB q hi
__device__ __nv_bfloat16 g_ql[(size_t)Bn * Nn * Dm];         // 2.4 MB q lo
__device__ float g_qn[(size_t)Bn * Nn];                      // 73 KB row |q|^2
__device__ float g_Z[(size_t)Bn * Nn];                       // 73 KB row sum of exp
__device__ __nv_bfloat16 g_ah[(size_t)Bn * Nn * Nn];         // 85 MB attn hi (unnormalized)
__device__ __nv_bfloat16 g_al[(size_t)Bn * Nn * Nn];         // 85 MB attn lo
__device__ __nv_bfloat16 g_xth[(size_t)Bn * Dd * Nn];        // 28 MB x^T hi
__device__ __nv_bfloat16 g_xtl[(size_t)Bn * Dd * Nn];        // 28 MB x^T lo
__device__ float g_xA[(size_t)Bn * Nn * Dd];                 // post-LN ping
__device__ float g_xT[(size_t)Bn * Nn * Dd];                 // pre-LN temp

// ---------------- base-target tensor-core helpers (sm_80+ PTX) ----------------
__device__ __forceinline__ uint32_t smem_u32(const void* p) {
    uint32_t r;
    asm("{ .reg .u64 t; cvta.to.shared.u64 t, %1; cvt.u32.u64 %0, t; }"
        : "=r"(r) : "l"(p));
    return r;
}

__device__ __forceinline__ void cp16(uint32_t dst, const void* src) {
    asm volatile("cp.async.cg.shared.global [%0], [%1], 16;"
                 :: "r"(dst), "l"(src) : "memory");
}
#define CP_COMMIT() asm volatile("cp.async.commit_group;" ::: "memory")
#define CP_WAIT(n)  asm volatile("cp.async.wait_group %0;" :: "n"(n) : "memory")

#define LDM_X4(r, addr) \
    asm volatile("ldmatrix.sync.aligned.m8n8.x4.shared.b16 {%0,%1,%2,%3}, [%4];" \
        : "=r"((r)[0]), "=r"((r)[1]), "=r"((r)[2]), "=r"((r)[3]) : "r"(addr))

#define MMA_BF16(c, a, b) \
    asm volatile("mma.sync.aligned.m16n8k16.row.col.f32.bf16.bf16.f32 " \
        "{%0,%1,%2,%3}, {%4,%5,%6,%7}, {%8,%9}, {%0,%1,%2,%3};" \
        : "+f"((c)[0]), "+f"((c)[1]), "+f"((c)[2]), "+f"((c)[3]) \
        : "r"((a)[0]), "r"((a)[1]), "r"((a)[2]), "r"((a)[3]), \
          "r"((b)[0]), "r"((b)[1]))

// ---------------- block reductions ----------------
__device__ __forceinline__ float block_sum256(float v, float* red) {
    #pragma unroll
    for (int o = 16; o; o >>= 1) v += __shfl_xor_sync(0xffffffffu, v, o);
    int tid = threadIdx.x;
    if ((tid & 31) == 0) red[tid >> 5] = v;
    __syncthreads();
    float t = red[0];
    #pragma unroll
    for (int w = 1; w < 8; w++) t += red[w];
    __syncthreads();
    return t;
}

// ======================================================================
// Kernel 1: q = x @ Wq + bq -> bf16 hi/lo split + per-row |q|^2 (fp32).
// Also zeroes g_Z for this layer (stream-ordered before simexp).
// ======================================================================
__global__ void __launch_bounds__(256)
qproj_kernel(const float* __restrict__ x, const float* __restrict__ Wq,
             const float* __restrict__ bq,
             __nv_bfloat16* __restrict__ qh, __nv_bfloat16* __restrict__ ql,
             float* __restrict__ qn, float* __restrict__ Zrow)
{
    __shared__ float As[64][32];
    __shared__ float Bs[32][64];
    const int tid = threadIdx.x;
    const int m0  = blockIdx.x * 64;
    const int ty  = tid >> 4, tx = tid & 15;

    float acc[4][4];
    #pragma unroll
    for (int i = 0; i < 4; i++)
        #pragma unroll
        for (int j = 0; j < 4; j++) acc[i][j] = 0.0f;

    for (int kt = 0; kt < Dd; kt += 32) {
        #pragma unroll
        for (int it = 0; it < 8; it++) {
            int idx = tid + it * 256;
            int m = idx >> 5, k = idx & 31;
            As[m][k] = x[(size_t)(m0 + m) * Dd + kt + k];
        }
        #pragma unroll
        for (int it = 0; it < 8; it++) {
            int idx = tid + it * 256;
            int k = idx >> 6, n = idx & 63;
            Bs[k][n] = Wq[(size_t)(kt + k) * Dm + n];
        }
        __syncthreads();
        #pragma unroll
        for (int k = 0; k < 32; k++) {
            float a[4], b[4];
            #pragma unroll
            for (int i = 0; i < 4; i++) a[i] = As[ty * 4 + i][k];
            #pragma unroll
            for (int j = 0; j < 4; j++) b[j] = Bs[k][tx * 4 + j];
            #pragma unroll
            for (int i = 0; i < 4; i++)
                #pragma unroll
                for (int j = 0; j < 4; j++) acc[i][j] = fmaf(a[i], b[j], acc[i][j]);
        }
        __syncthreads();
    }

    float sq[4] = {0.0f, 0.0f, 0.0f, 0.0f};
    #pragma unroll
    for (int i = 0; i < 4; i++)
        #pragma unroll
        for (int j = 0; j < 4; j++) {
            float v = acc[i][j] + bq[tx * 4 + j];
            sq[i] += v * v;
            __nv_bfloat16 h = __float2bfloat16(v);
            __nv_bfloat16 l = __float2bfloat16(v - __bfloat162float(h));
            size_t o = (size_t)(m0 + ty * 4 + i) * Dm + tx * 4 + j;
            qh[o] = h;
            ql[o] = l;
        }

    #pragma unroll
    for (int i = 0; i < 4; i++) {
        float s = sq[i];
        #pragma unroll
        for (int o = 1; o < 16; o <<= 1) s += __shfl_xor_sync(0xffffffffu, s, o);
        if (tx == 0) {
            qn[m0 + ty * 4 + i] = s;
            Zrow[m0 + ty * 4 + i] = 0.0f;     // zero rowsum accumulator
        }
    }
}

// ======================================================================
// Kernel 2: attn_unnorm = exp(scale*q@q^T - diag_i) via mma.sync bf16.
//   Epilogue: exp -> bf16 hi/lo + per-row sum Z via quad-reduce+atomicAdd.
//   Downstream LN uses eps*Z^2, making the skipped 1/Z normalization EXACT.
// ======================================================================
#define SROW 144
#define SARR (128 * SROW)           // 18432
#define SIM_SMEM (4 * SARR)         // 73728

__global__ void __launch_bounds__(256)
simexp_kernel(const __nv_bfloat16* __restrict__ qh,
              const __nv_bfloat16* __restrict__ ql,
              const float* __restrict__ qn,
              __nv_bfloat16* __restrict__ ah,
              __nv_bfloat16* __restrict__ al,
              float* __restrict__ Zrow)
{
    extern __shared__ __align__(128) char dsm[];

    const int tid  = threadIdx.x;
    const int wid  = tid >> 5;
    const int lane = tid & 31;
    const int warp_m = wid >> 2;          // 0..1
    const int warp_n = wid & 3;           // 0..3
    const int b  = blockIdx.z;
    const int j0 = blockIdx.x * 128;
    const int i0 = blockIdx.y * 128;

    const uint32_t sbase = smem_u32(dsm);
    const __nv_bfloat16* qh_b = qh + (size_t)b * Nn * Dm;
    const __nv_bfloat16* ql_b = ql + (size_t)b * Nn * Dm;
    const float* qn_b = qn + (size_t)b * Nn;
    float* Zb = Zrow + (size_t)b * Nn;

    #pragma unroll
    for (int t = 0; t < 16; t++) {
        int idx = tid + t * 256;
        int arr = idx >> 10;              // 0:Qi_h 1:Qi_l 2:Qj_h 3:Qj_l
        int r   = (idx >> 3) & 127;
        int j   = idx & 7;
        const __nv_bfloat16* base = (arr == 0 || arr == 2) ? qh_b : ql_b;
        int grow = (arr < 2) ? (i0 + r) : (j0 + r);
        cp16(sbase + (uint32_t)(arr * SARR + r * SROW + j * 16),
             base + (size_t)grow * Dm + j * 8);
    }
    CP_COMMIT();
    CP_WAIT(0);
    __syncthreads();

    float acc[4][4][4];
    #pragma unroll
    for (int mi = 0; mi < 4; mi++)
        #pragma unroll
        for (int ni = 0; ni < 4; ni++)
            #pragma unroll
            for (int k = 0; k < 4; k++) acc[mi][ni][k] = 0.0f;

    const int tq = lane >> 3;
    const int i7 = lane & 7;
    const uint32_t a_row = (uint32_t)(warp_m * 64 + ((tq & 1) << 3) + i7);
    const uint32_t a_kb  = (uint32_t)((tq >> 1) << 4);
    const uint32_t b_row = (uint32_t)(warp_n * 32 + ((tq >> 1) << 3) + i7);
    const uint32_t b_kb  = (uint32_t)((tq & 1) << 4);

    #pragma unroll
    for (int ks = 0; ks < 4; ks++) {
        const uint32_t koff = (uint32_t)(ks * 32);

        uint32_t ah_f[4][4], al_f[4][4];
        uint32_t bh_f[4][2], bl_f[4][2];

        #pragma unroll
        for (int mi = 0; mi < 4; mi++) {
            uint32_t addr = sbase + (a_row + mi * 16) * SROW + koff + a_kb;
            LDM_X4(ah_f[mi], addr);
            LDM_X4(al_f[mi], addr + SARR);
        }
        #pragma unroll
        for (int nj = 0; nj < 2; nj++) {
            uint32_t addr = sbase + 2 * SARR + (b_row + nj * 16) * SROW + koff + b_kb;
            uint32_t r[4];
            LDM_X4(r, addr);
            bh_f[nj * 2][0] = r[0]; bh_f[nj * 2][1] = r[1];
            bh_f[nj * 2 + 1][0] = r[2]; bh_f[nj * 2 + 1][1] = r[3];
            LDM_X4(r, addr + SARR);
            bl_f[nj * 2][0] = r[0]; bl_f[nj * 2][1] = r[1];
            bl_f[nj * 2 + 1][0] = r[2]; bl_f[nj * 2 + 1][1] = r[3];
        }

        #pragma unroll
        for (int mi = 0; mi < 4; mi++)
            #pragma unroll
            for (int ni = 0; ni < 4; ni++) {
                MMA_BF16(acc[mi][ni], ah_f[mi], bh_f[ni]);
                MMA_BF16(acc[mi][ni], ah_f[mi], bl_f[ni]);
                MMA_BF16(acc[mi][ni], al_f[mi], bh_f[ni]);
            }
    }

    // epilogue: exp(logit - C_row) -> bf16 hi/lo + row-sum accumulation
    const int g  = lane >> 2;
    const int t2 = (lane & 3) * 2;
    __nv_bfloat16* ahb = ah + (size_t)b * Nn * Nn;
    __nv_bfloat16* alb = al + (size_t)b * Nn * Nn;
    #pragma unroll
    for (int mi = 0; mi < 4; mi++) {
        const int r0 = i0 + warp_m * 64 + mi * 16 + g;
        const float C0 = qn_b[r0] * K_SCALE;
        const float C1 = qn_b[r0 + 8] * K_SCALE;
        float z0 = 0.0f, z1 = 0.0f;
        #pragma unroll
        for (int ni = 0; ni < 4; ni++) {
            const int col = j0 + warp_n * 32 + ni * 8 + t2;
            float e00 = __expf(fmaf(acc[mi][ni][0], K_SCALE, -C0));
            float e01 = __expf(fmaf(acc[mi][ni][1], K_SCALE, -C0));
            float e10 = __expf(fmaf(acc[mi][ni][2], K_SCALE, -C1));
            float e11 = __expf(fmaf(acc[mi][ni][3], K_SCALE, -C1));
            z0 += e00 + e01;
            z1 += e10 + e11;

            __nv_bfloat162 h0, l0, h1, l1;
            h0.x = __float2bfloat16(e00);
            h0.y = __float2bfloat16(e01);
            l0.x = __float2bfloat16(e00 - __bfloat162float(h0.x));
            l0.y = __float2bfloat16(e01 - __bfloat162float(h0.y));
            h1.x = __float2bfloat16(e10);
            h1.y = __float2bfloat16(e11);
            l1.x = __float2bfloat16(e10 - __bfloat162float(h1.x));
            l1.y = __float2bfloat16(e11 - __bfloat162float(h1.y));

            *(__nv_bfloat162*)&ahb[(size_t)r0 * Nn + col] = h0;
            *(__nv_bfloat162*)&alb[(size_t)r0 * Nn + col] = l0;
            *(__nv_bfloat162*)&ahb[(size_t)(r0 + 8) * Nn + col] = h1;
            *(__nv_bfloat162*)&alb[(size_t)(r0 + 8) * Nn + col] = l1;
        }
        // reduce across the 4 lanes of the quad (same row, different cols)
        z0 += __shfl_xor_sync(0xffffffffu, z0, 1);
        z0 += __shfl_xor_sync(0xffffffffu, z0, 2);
        z1 += __shfl_xor_sync(0xffffffffu, z1, 1);
        z1 += __shfl_xor_sync(0xffffffffu, z1, 2);
        if ((lane & 3) == 0) {
            atomicAdd(&Zb[r0], z0);
            atomicAdd(&Zb[r0 + 8], z1);
        }
    }
}

// ======================================================================
// Kernel 3b: transpose + bf16 hi/lo split of x: [B,N,D] -> [B,D,N]
// ======================================================================
__global__ void __launch_bounds__(256)
xsplitT_kernel(const float* __restrict__ x,
               __nv_bfloat16* __restrict__ xth, __nv_bfloat16* __restrict__ xtl)
{
    __shared__ float tile[32][33];
    const int b = blockIdx.z;
    const int tok0 = blockIdx.x * 32;
    const int d0   = blockIdx.y * 32;
    const int tx = threadIdx.x & 31;
    const int ty = threadIdx.x >> 5;       // 0..7

    const float* xb = x + (size_t)b * Nn * Dd;
    #pragma unroll
    for (int i = 0; i < 4; i++)
        tile[ty + i * 8][tx] = xb[(size_t)(tok0 + ty + i * 8) * Dd + d0 + tx];
    __syncthreads();

    #pragma unroll
    for (int i = 0; i < 4; i++) {
        float v = tile[tx][ty + i * 8];
        __nv_bfloat16 h = __float2bfloat16(v);
        __nv_bfloat16 l = __float2bfloat16(v - __bfloat162float(h));
        size_t o = (size_t)b * Dd * Nn + (size_t)(d0 + ty + i * 8) * Nn + tok0 + tx;
        xth[o] = h;
        xtl[o] = l;
    }
}

// ======================================================================
// Kernel 4: mma.sync bf16 split GEMM: C = attn_unnorm @ x
// ======================================================================
#define AROW 80
#define ARR_BYTES (128 * AROW)        // 10240
#define STAGE_BYTES (4 * ARR_BYTES)   // 40960
#define GEMM_SMEM (2 * STAGE_BYTES)   // 81920
#define NCHUNK (Nn / 32)              // 72

__global__ void __launch_bounds__(256)
gemm_av_mma_kernel(const __nv_bfloat16* __restrict__ Ah,
                   const __nv_bfloat16* __restrict__ Al,
                   const __nv_bfloat16* __restrict__ Bh,
                   const __nv_bfloat16* __restrict__ Bl,
                   float* __restrict__ C)
{
    extern __shared__ __align__(128) char dsm[];

    const int tid  = threadIdx.x;
    const int wid  = tid >> 5;
    const int lane = tid & 31;
    const int warp_m = wid >> 2;
    const int warp_n = wid & 3;
    const int b  = blockIdx.z;
    const int n0 = blockIdx.x * 128;
    const int m0 = blockIdx.y * 128;

    const uint32_t sbase = smem_u32(dsm);

    const __nv_bfloat16* Ah_b = Ah + (size_t)b * Nn * Nn;
    const __nv_bfloat16* Al_b = Al + (size_t)b * Nn * Nn;
    const __nv_bfloat16* Bh_b = Bh + (size_t)b * Dd * Nn;
    const __nv_bfloat16* Bl_b = Bl + (size_t)b * Dd * Nn;

    const __nv_bfloat16* src_row[8];
    uint32_t dst_off[8];
    #pragma unroll
    for (int t = 0; t < 8; t++) {
        int idx = tid + t * 256;
        int arr = idx >> 9;
        int r   = (idx >> 2) & 127;
        int j   = idx & 3;
        const __nv_bfloat16* base =
            (arr == 0) ? Ah_b : (arr == 1) ? Al_b : (arr == 2) ? Bh_b : Bl_b;
        int grow = (arr < 2) ? (m0 + r) : (n0 + r);
        src_row[t] = base + (size_t)grow * Nn + j * 8;
        dst_off[t] = (uint32_t)(arr * ARR_BYTES + r * AROW + j * 16);
    }

    float acc[4][4][4];
    #pragma unroll
    for (int mi = 0; mi < 4; mi++)
        #pragma unroll
        for (int ni = 0; ni < 4; ni++)
            #pragma unroll
            for (int k = 0; k < 4; k++) acc[mi][ni][k] = 0.0f;

    #pragma unroll
    for (int t = 0; t < 8; t++) cp16(sbase + dst_off[t], src_row[t]);
    CP_COMMIT();

    const int tq  = lane >> 3;
    const int i7  = lane & 7;
    const uint32_t a_row = (uint32_t)(warp_m * 64 + ((tq & 1) << 3) + i7);
    const uint32_t a_kb  = (uint32_t)((tq >> 1) << 4);
    const uint32_t b_row = (uint32_t)(warp_n * 32 + ((tq >> 1) << 3) + i7);
    const uint32_t b_kb  = (uint32_t)((tq & 1) << 4);

    for (int c = 0; c < NCHUNK; c++) {
        if (c + 1 < NCHUNK) {
            const int k0 = (c + 1) * 32;
            const uint32_t sdst = sbase + ((c + 1) & 1) * STAGE_BYTES;
            #pragma unroll
            for (int t = 0; t < 8; t++) cp16(sdst + dst_off[t], src_row[t] + k0);
            CP_COMMIT();
            CP_WAIT(1);
        } else {
            CP_WAIT(0);
        }
        __syncthreads();

        const uint32_t sb = sbase + (c & 1) * STAGE_BYTES;

        #pragma unroll
        for (int ks = 0; ks < 2; ks++) {
            const uint32_t koff = (uint32_t)(ks * 32);

            uint32_t ah_f[4][4], al_f[4][4];
            uint32_t bh_f[4][2], bl_f[4][2];

            #pragma unroll
            for (int mi = 0; mi < 4; mi++) {
                uint32_t addr = sb + (a_row + mi * 16) * AROW + koff + a_kb;
                LDM_X4(ah_f[mi], addr);
                LDM_X4(al_f[mi], addr + ARR_BYTES);
            }
            #pragma unroll
            for (int nj = 0; nj < 2; nj++) {
                uint32_t addr = sb + 2 * ARR_BYTES + (b_row + nj * 16) * AROW + koff + b_kb;
                uint32_t r[4];
                LDM_X4(r, addr);
                bh_f[nj * 2][0] = r[0]; bh_f[nj * 2][1] = r[1];
                bh_f[nj * 2 + 1][0] = r[2]; bh_f[nj * 2 + 1][1] = r[3];
                LDM_X4(r, addr + ARR_BYTES);
                bl_f[nj * 2][0] = r[0]; bl_f[nj * 2][1] = r[1];
                bl_f[nj * 2 + 1][0] = r[2]; bl_f[nj * 2 + 1][1] = r[3];
            }

            #pragma unroll
            for (int mi = 0; mi < 4; mi++)
                #pragma unroll
                for (int ni = 0; ni < 4; ni++) {
                    MMA_BF16(acc[mi][ni], ah_f[mi], bh_f[ni]);
                    MMA_BF16(acc[mi][ni], ah_f[mi], bl_f[ni]);
                    MMA_BF16(acc[mi][ni], al_f[mi], bh_f[ni]);
                }
        }
        __syncthreads();
    }

    const int g  = lane >> 2;
    const int t2 = (lane & 3) * 2;
    float* Cb = C + (size_t)b * Nn * Dd;
    #pragma unroll
    for (int mi = 0; mi < 4; mi++) {
        const int row0 = m0 + warp_m * 64 + mi * 16 + g;
        #pragma unroll
        for (int ni = 0; ni < 4; ni++) {
            const int col = n0 + warp_n * 32 + ni * 8 + t2;
            *(float2*)&Cb[(size_t)row0 * Dd + col] =
                make_float2(acc[mi][ni][0], acc[mi][ni][1]);
            *(float2*)&Cb[(size_t)(row0 + 8) * Dd + col] =
                make_float2(acc[mi][ni][2], acc[mi][ni][3]);
        }
    }
}

// ======================================================================
// Kernel 5: layernorm over last dim (768). One block per row.
// Input row is Z * v (unnormalized attention); using eps*Z^2 makes
// the output EXACTLY equal LN(v) with eps: rows scale out of mean/var.
// ======================================================================
__global__ void __launch_bounds__(256)
ln_kernel(const float* __restrict__ xin, const float* __restrict__ gamma,
          const float* __restrict__ beta, const float* __restrict__ Zrow,
          float* __restrict__ xout)
{
    __shared__ float red[8];
    const size_t row = blockIdx.x;
    const float* p = xin + row * (size_t)Dd;
    float* o = xout + row * (size_t)Dd;
    const int tid = threadIdx.x;

    const float Z = Zrow[row];
    const float epsZ = LN_EPS * Z * Z;

    float v[3];
    #pragma unroll
    for (int i = 0; i < 3; i++) v[i] = p[tid + i * 256];

    float s = v[0] + v[1] + v[2];
    s = block_sum256(s, red);
    const float mu = s * (1.0f / Dd);

    float d2 = 0.0f;
    #pragma unroll
    for (int i = 0; i < 3; i++) { float d = v[i] - mu; d2 += d * d; }
    d2 = block_sum256(d2, red);
    const float rs = rsqrtf(d2 * (1.0f / Dd) + epsZ);

    #pragma unroll
    for (int i = 0; i < 3; i++) {
        int c = tid + i * 256;
        o[c] = (v[i] - mu) * rs * gamma[c] + beta[c];
    }
}

// ======================================================================
// launch
// ======================================================================
extern "C" void kernel_launch(void* const* d_in, const int* in_sizes, int n_in,
                              void* d_out, int out_size)
{
    (void)in_sizes; (void)n_in; (void)out_size;
    const float* x     = (const float*)d_in[0];
    const float* Wq    = (const float*)d_in[1];
    const float* bq    = (const float*)d_in[2];
    const float* gamma = (const float*)d_in[3];
    const float* beta  = (const float*)d_in[4];
    float* out = (float*)d_out;

    float *xa, *xt, *qn, *Zr;
    __nv_bfloat16 *qhp, *qlp, *ah, *al, *xth, *xtl;
    cudaGetSymbolAddress((void**)&qhp,  g_qh);
    cudaGetSymbolAddress((void**)&qlp,  g_ql);
    cudaGetSymbolAddress((void**)&qn,   g_qn);
    cudaGetSymbolAddress((void**)&Zr,   g_Z);
    cudaGetSymbolAddress((void**)&ah,   g_ah);
    cudaGetSymbolAddress((void**)&al,   g_al);
    cudaGetSymbolAddress((void**)&xth,  g_xth);
    cudaGetSymbolAddress((void**)&xtl,  g_xtl);
    cudaGetSymbolAddress((void**)&xa,   g_xA);
    cudaGetSymbolAddress((void**)&xt,   g_xT);

    cudaFuncSetAttribute(gemm_av_mma_kernel,
                         cudaFuncAttributeMaxDynamicSharedMemorySize, GEMM_SMEM);
    cudaFuncSetAttribute(simexp_kernel,
                         cudaFuncAttributeMaxDynamicSharedMemorySize, SIM_SMEM);

    const int rows = Bn * Nn;                 // 18432
    const float* xin = x;
    float* lnout[3] = { xa, xa, out };

    for (int l = 0; l < 3; l++) {
        qproj_kernel      <<< rows / 64, 256 >>>(xin, Wq, bq, qhp, qlp, qn, Zr);
        simexp_kernel     <<< dim3(Nn / 128, Nn / 128, Bn), 256, SIM_SMEM >>>
                              (qhp, qlp, qn, ah, al, Zr);
        xsplitT_kernel    <<< dim3(Nn / 32, Dd / 32, Bn), 256 >>>(xin, xth, xtl);
        gemm_av_mma_kernel<<< dim3(Dd / 128, Nn / 128, Bn), 256, GEMM_SMEM >>>
                              (ah, al, xth, xtl, xt);
        ln_kernel         <<< rows, 256 >>>(xt, gamma, beta, Zr, lnout[l]);
        xin = lnout[l];
    }
}